// round 2
// baseline (speedup 1.0000x reference)
#include <cuda_runtime.h>

#define NMAX 50000
#define EMAX 800000
#define D    64
#define D2   32

// ---------------- scratch (device globals) ----------------------------------
__device__ float d_buf0[NMAX * D];
__device__ float d_buf1[NMAX * D];
__device__ float d_acc [NMAX * D];
__device__ float d_g   [NMAX * D];
__device__ float d_hid [NMAX * D];
__device__ float d_g2  [NMAX * D2];
__device__ float d_p   [NMAX];
__device__ float d_q   [NMAX];
__device__ float d_invdeg[NMAX];
__device__ int   d_cnt [NMAX];
__device__ int   d_rowptr[NMAX + 1];
__device__ int   d_cursor[NMAX];
__device__ int   d_col [EMAX];
__device__ int   d_bsum[256];

// ---------------- CSR build --------------------------------------------------
__global__ void k_zero_cnt(int n) {
    int i = blockIdx.x * blockDim.x + threadIdx.x;
    if (i < n) d_cnt[i] = 0;
}

__global__ void k_count(const int* __restrict__ dst, int e) {
    for (int i = blockIdx.x * blockDim.x + threadIdx.x; i < e;
         i += gridDim.x * blockDim.x)
        atomicAdd(&d_cnt[dst[i]], 1);
}

// 1024-thread block-local exclusive scan; block sums -> d_bsum
__global__ void k_scanA(int n) {
    __shared__ int sh[1024];
    int i = blockIdx.x * 1024 + threadIdx.x;
    int v = (i < n) ? d_cnt[i] : 0;
    sh[threadIdx.x] = v;
    __syncthreads();
#pragma unroll
    for (int off = 1; off < 1024; off <<= 1) {
        int t = (threadIdx.x >= off) ? sh[threadIdx.x - off] : 0;
        __syncthreads();
        sh[threadIdx.x] += t;
        __syncthreads();
    }
    if (i < n) d_rowptr[i] = sh[threadIdx.x] - v;
    if (threadIdx.x == 1023) d_bsum[blockIdx.x] = sh[1023];
}

// parallel scan of block sums (nb <= 128)
__global__ void k_scanB(int nb) {
    __shared__ int sh[128];
    int t = threadIdx.x;
    int v = (t < nb) ? d_bsum[t] : 0;
    sh[t] = v;
    __syncthreads();
#pragma unroll
    for (int off = 1; off < 128; off <<= 1) {
        int u = (t >= off) ? sh[t - off] : 0;
        __syncthreads();
        sh[t] += u;
        __syncthreads();
    }
    if (t < nb) d_bsum[t] = sh[t] - v;  // exclusive
}

__global__ void k_scanC(int n, int e) {
    int i = blockIdx.x * blockDim.x + threadIdx.x;
    if (i >= n) return;
    int rp = d_rowptr[i] + d_bsum[i >> 10];
    d_rowptr[i] = rp;
    d_cursor[i] = rp;
    int c = d_cnt[i];
    d_invdeg[i] = 1.0f / (float)(c > 1 ? c : 1);
    if (i == 0) d_rowptr[n] = e;
}

__global__ void k_fill(const int* __restrict__ src, const int* __restrict__ dst, int e) {
    for (int i = blockIdx.x * blockDim.x + threadIdx.x; i < e;
         i += gridDim.x * blockDim.x) {
        int dd  = dst[i];
        int pos = atomicAdd(&d_cursor[dd], 1);
        d_col[pos] = src[i];
    }
}

// ---------------- smoothing pass: hout = mean_in(hin); acc (+)= hout ---------
// mode bit0: init acc from hin[w]; bit1: write hout
__global__ void k_pass(const float* __restrict__ hin, float* __restrict__ hout,
                       int mode, int n) {
    int w    = (blockIdx.x * blockDim.x + threadIdx.x) >> 5;
    int lane = threadIdx.x & 31;
    if (w >= n) return;
    int beg = d_rowptr[w], end = d_rowptr[w + 1];
    const float2* __restrict__ h2 = (const float2*)hin;
    float a0 = 0.f, a1 = 0.f;
    int ei = beg;
    for (; ei + 4 <= end; ei += 4) {
        int s0 = d_col[ei], s1 = d_col[ei + 1], s2 = d_col[ei + 2], s3 = d_col[ei + 3];
        float2 v0 = h2[s0 * 32 + lane];
        float2 v1 = h2[s1 * 32 + lane];
        float2 v2 = h2[s2 * 32 + lane];
        float2 v3 = h2[s3 * 32 + lane];
        a0 += (v0.x + v1.x) + (v2.x + v3.x);
        a1 += (v0.y + v1.y) + (v2.y + v3.y);
    }
    for (; ei < end; ei++) {
        int s = d_col[ei];
        float2 v = h2[s * 32 + lane];
        a0 += v.x; a1 += v.y;
    }
    float inv = d_invdeg[w];
    a0 *= inv; a1 *= inv;
    if (mode & 2) ((float2*)hout)[w * 32 + lane] = make_float2(a0, a1);
    float2* acc2 = (float2*)d_acc;
    if (mode & 1) {
        float2 xv = h2[w * 32 + lane];
        acc2[w * 32 + lane] = make_float2(xv.x + a0, xv.y + a1);
    } else {
        float2 t = acc2[w * 32 + lane];
        acc2[w * 32 + lane] = make_float2(t.x + a0, t.y + a1);
    }
}

// ---------------- node GEMM: out[n,M] = (hin[n,64]*scale) @ W[64,M] ----------
template <int M>
__global__ void k_gemm(const float* __restrict__ hin, float scale,
                       const float* __restrict__ W, float* __restrict__ out, int n) {
    constexpr int NPG = 128 / M;
    __shared__ float Wsh[64 * M];
    __shared__ float xr[NPG][64];
    int o  = threadIdx.x % M;
    int ln = threadIdx.x / M;
    for (int idx = threadIdx.x; idx < 64 * M; idx += 128) Wsh[idx] = W[idx];
    __syncthreads();
    for (int base = blockIdx.x * NPG; base < n; base += gridDim.x * NPG) {
        int node = base + ln;
        if (node < n)
            for (int k = o; k < 64; k += M) xr[ln][k] = hin[node * 64 + k] * scale;
        __syncthreads();
        if (node < n) {
            float acc = 0.f;
#pragma unroll
            for (int k = 0; k < 64; k++) acc += xr[ln][k] * Wsh[k * M + o];
            out[node * M + o] = acc;
        }
        __syncthreads();
    }
}

// ---------------- p/q per node ------------------------------------------------
__global__ void k_pq(const float* __restrict__ hin, float scale,
                     const float* __restrict__ Watt,
                     float* __restrict__ p, float* __restrict__ q, int n) {
    int w    = (blockIdx.x * blockDim.x + threadIdx.x) >> 5;
    int lane = threadIdx.x & 31;
    if (w >= n) return;
    float x0 = hin[w * 64 + lane] * scale;
    float x1 = hin[w * 64 + lane + 32] * scale;
    float pp = x0 * Watt[lane]      + x1 * Watt[lane + 32];
    float qq = x0 * Watt[64 + lane] + x1 * Watt[96 + lane];
#pragma unroll
    for (int off = 16; off; off >>= 1) {
        pp += __shfl_down_sync(0xffffffffu, pp, off);
        qq += __shfl_down_sync(0xffffffffu, qq, off);
    }
    if (lane == 0) { p[w] = pp; q[w] = qq; }
}

// ---------------- conv1 edge aggregation (64-wide, + relu) -------------------
__global__ void k_edge64(const float* __restrict__ g, const float* __restrict__ p,
                         const float* __restrict__ q, const float* __restrict__ batt,
                         float* __restrict__ out, int n) {
    int w    = (blockIdx.x * blockDim.x + threadIdx.x) >> 5;
    int lane = threadIdx.x & 31;
    if (w >= n) return;
    float qi = q[w] + batt[0];
    const float2* __restrict__ g2 = (const float2*)g;
    float a0 = 0.f, a1 = 0.f;
    int beg = d_rowptr[w], end = d_rowptr[w + 1];
    int ei = beg;
    for (; ei + 4 <= end; ei += 4) {
        int s0 = d_col[ei], s1 = d_col[ei + 1], s2 = d_col[ei + 2], s3 = d_col[ei + 3];
        float p0 = p[s0], p1 = p[s1], p2 = p[s2], p3 = p[s3];
        float2 v0 = g2[s0 * 32 + lane];
        float2 v1 = g2[s1 * 32 + lane];
        float2 v2 = g2[s2 * 32 + lane];
        float2 v3 = g2[s3 * 32 + lane];
        float c0 = p0 + qi; c0 = c0 > 0.f ? c0 : 0.01f * c0;
        float c1 = p1 + qi; c1 = c1 > 0.f ? c1 : 0.01f * c1;
        float c2 = p2 + qi; c2 = c2 > 0.f ? c2 : 0.01f * c2;
        float c3 = p3 + qi; c3 = c3 > 0.f ? c3 : 0.01f * c3;
        a0 += c0 * v0.x + c1 * v1.x + c2 * v2.x + c3 * v3.x;
        a1 += c0 * v0.y + c1 * v1.y + c2 * v2.y + c3 * v3.y;
    }
    for (; ei < end; ei++) {
        int s = d_col[ei];
        float sc = p[s] + qi;
        sc = sc > 0.f ? sc : 0.01f * sc;
        float2 v = g2[s * 32 + lane];
        a0 += sc * v.x; a1 += sc * v.y;
    }
    ((float2*)out)[w * 32 + lane] = make_float2(fmaxf(a0, 0.f), fmaxf(a1, 0.f));
}

// ---------------- conv2 edge aggregation (32-wide, final) --------------------
__global__ void k_edge32(const float* __restrict__ g, const float* __restrict__ p,
                         const float* __restrict__ q, const float* __restrict__ batt,
                         float* __restrict__ out, int n) {
    int w    = (blockIdx.x * blockDim.x + threadIdx.x) >> 5;
    int lane = threadIdx.x & 31;
    if (w >= n) return;
    float qi = q[w] + batt[0];
    float a0 = 0.f;
    int beg = d_rowptr[w], end = d_rowptr[w + 1];
    int ei = beg;
    for (; ei + 4 <= end; ei += 4) {
        int s0 = d_col[ei], s1 = d_col[ei + 1], s2 = d_col[ei + 2], s3 = d_col[ei + 3];
        float p0 = p[s0], p1 = p[s1], p2 = p[s2], p3 = p[s3];
        float v0 = g[s0 * 32 + lane];
        float v1 = g[s1 * 32 + lane];
        float v2 = g[s2 * 32 + lane];
        float v3 = g[s3 * 32 + lane];
        float c0 = p0 + qi; c0 = c0 > 0.f ? c0 : 0.01f * c0;
        float c1 = p1 + qi; c1 = c1 > 0.f ? c1 : 0.01f * c1;
        float c2 = p2 + qi; c2 = c2 > 0.f ? c2 : 0.01f * c2;
        float c3 = p3 + qi; c3 = c3 > 0.f ? c3 : 0.01f * c3;
        a0 += c0 * v0 + c1 * v1 + c2 * v2 + c3 * v3;
    }
    for (; ei < end; ei++) {
        int s = d_col[ei];
        float sc = p[s] + qi;
        sc = sc > 0.f ? sc : 0.01f * sc;
        a0 += sc * g[s * 32 + lane];
    }
    out[w * 32 + lane] = a0;
}

// ---------------- launch ------------------------------------------------------
extern "C" void kernel_launch(void* const* d_in, const int* in_sizes, int n_in,
                              void* d_out, int out_size) {
    const float* x     = (const float*)d_in[0];
    const int*   ei    = (const int*)  d_in[1];
    const float* Watt1 = (const float*)d_in[2];
    const float* batt1 = (const float*)d_in[3];
    const float* Wlin1 = (const float*)d_in[4];
    const float* Watt2 = (const float*)d_in[5];
    const float* batt2 = (const float*)d_in[6];
    const float* Wlin2 = (const float*)d_in[7];

    int n = in_sizes[0] / D;   // 50000
    int e = in_sizes[1] / 2;   // 800000
    const int* src = ei;
    const int* dst = ei + e;

    float *buf0, *buf1, *accp, *gp, *hidp, *g2p, *pp, *qp;
    cudaGetSymbolAddress((void**)&buf0, d_buf0);
    cudaGetSymbolAddress((void**)&buf1, d_buf1);
    cudaGetSymbolAddress((void**)&accp, d_acc);
    cudaGetSymbolAddress((void**)&gp,   d_g);
    cudaGetSymbolAddress((void**)&hidp, d_hid);
    cudaGetSymbolAddress((void**)&g2p,  d_g2);
    cudaGetSymbolAddress((void**)&pp,   d_p);
    cudaGetSymbolAddress((void**)&qp,   d_q);

    const int TB = 256;
    int nblk   = (n + TB - 1) / TB;
    int nb1024 = (n + 1023) / 1024;
    int wb     = (n * 32 + TB - 1) / TB;

    // CSR build
    k_zero_cnt<<<nblk, TB>>>(n);
    k_count<<<592, TB>>>(dst, e);
    k_scanA<<<nb1024, 1024>>>(n);
    k_scanB<<<1, 128>>>(nb1024);
    k_scanC<<<nblk, TB>>>(n, e);
    k_fill<<<592, TB>>>(src, dst, e);

    // graphSmoothing: acc = x + m(x) + m^2(x) + m^3(x)
    k_pass<<<wb, TB>>>(x,    buf0, 3, n);  // init acc + write hout
    k_pass<<<wb, TB>>>(buf0, buf1, 2, n);  // write hout
    k_pass<<<wb, TB>>>(buf1, buf0, 0, n);  // acc only (hout dead)

    // conv1 (scale 0.25 folds xs = acc/4)
    k_gemm<64><<<592, 128>>>(accp, 0.25f, Wlin1, gp, n);
    k_pq<<<wb, TB>>>(accp, 0.25f, Watt1, pp, qp, n);
    k_edge64<<<wb, TB>>>(gp, pp, qp, batt1, hidp, n);

    // conv2
    k_gemm<32><<<592, 128>>>(hidp, 1.0f, Wlin2, g2p, n);
    k_pq<<<wb, TB>>>(hidp, 1.0f, Watt2, pp, qp, n);
    k_edge32<<<wb, TB>>>(g2p, pp, qp, batt2, (float*)d_out, n);
}

// round 3
// speedup vs baseline: 1.0063x; 1.0063x over previous
#include <cuda_runtime.h>

#define NMAX 50000
#define EMAX 800000
#define FULL 0xffffffffu

// ---------------- scratch (device globals) ----------------------------------
__device__ float d_buf0[NMAX * 64];
__device__ float d_buf1[NMAX * 64];
__device__ float d_acc [NMAX * 64];
__device__ float d_g   [NMAX * 64];
__device__ float d_hid [NMAX * 64];
__device__ float d_g2  [NMAX * 32];
__device__ float d_p   [NMAX];
__device__ float d_q   [NMAX];
__device__ float d_p2  [NMAX];
__device__ float d_q2  [NMAX];
__device__ float d_invdeg[NMAX];
__device__ int   d_cnt [NMAX];
__device__ int   d_rowptr[NMAX + 1];
__device__ int   d_cursor[NMAX];
__device__ int   d_col [EMAX];
__device__ int   d_bsum[128];

// ---------------- CSR build --------------------------------------------------
__global__ void k_zero_cnt(int n) {
    int i = blockIdx.x * blockDim.x + threadIdx.x;
    if (i < n) d_cnt[i] = 0;
}

__global__ void k_count(const int* __restrict__ dst, int e) {
    for (int i = blockIdx.x * blockDim.x + threadIdx.x; i < e;
         i += gridDim.x * blockDim.x)
        atomicAdd(&d_cnt[dst[i]], 1);
}

__global__ void k_scanA(int n) {
    __shared__ int sh[1024];
    int i = blockIdx.x * 1024 + threadIdx.x;
    int v = (i < n) ? d_cnt[i] : 0;
    sh[threadIdx.x] = v;
    __syncthreads();
#pragma unroll
    for (int off = 1; off < 1024; off <<= 1) {
        int t = (threadIdx.x >= off) ? sh[threadIdx.x - off] : 0;
        __syncthreads();
        sh[threadIdx.x] += t;
        __syncthreads();
    }
    if (i < n) d_rowptr[i] = sh[threadIdx.x] - v;
    if (threadIdx.x == 1023) d_bsum[blockIdx.x] = sh[1023];
}

__global__ void k_scanB(int nb) {
    __shared__ int sh[128];
    int t = threadIdx.x;
    int v = (t < nb) ? d_bsum[t] : 0;
    sh[t] = v;
    __syncthreads();
#pragma unroll
    for (int off = 1; off < 128; off <<= 1) {
        int u = (t >= off) ? sh[t - off] : 0;
        __syncthreads();
        sh[t] += u;
        __syncthreads();
    }
    if (t < nb) d_bsum[t] = sh[t] - v;
}

__global__ void k_scanC(int n, int e) {
    int i = blockIdx.x * blockDim.x + threadIdx.x;
    if (i >= n) return;
    int rp = d_rowptr[i] + d_bsum[i >> 10];
    d_rowptr[i] = rp;
    d_cursor[i] = rp;
    int c = d_cnt[i];
    d_invdeg[i] = 1.0f / (float)(c > 1 ? c : 1);
    if (i == 0) d_rowptr[n] = e;
}

__global__ void k_fill(const int* __restrict__ src, const int* __restrict__ dst, int e) {
    for (int i = blockIdx.x * blockDim.x + threadIdx.x; i < e;
         i += gridDim.x * blockDim.x) {
        int dd  = dst[i];
        int pos = atomicAdd(&d_cursor[dd], 1);
        d_col[pos] = src[i];
    }
}

// ---------------- smoothing pass (float4 pair-gather) ------------------------
// MODE 1: pass1  (acc = x + mean, write hout)
// MODE 2: pass2  (acc += mean, write hout)
// MODE 4: pass3  (acc += mean, no hout, fused p/q for conv1 with 0.25 scale)
template <int MODE>
__global__ void k_pass(const float* __restrict__ hin, float* __restrict__ hout,
                       const float* __restrict__ Watt, int n) {
    int w    = (blockIdx.x * blockDim.x + threadIdx.x) >> 5;
    int lane = threadIdx.x & 31;
    if (w >= n) return;
    int beg = d_rowptr[w], end = d_rowptr[w + 1];
    const float4* __restrict__ h4 = (const float4*)hin;
    int half = lane >> 4, sub = lane & 15;
    float4 a = make_float4(0.f, 0.f, 0.f, 0.f);
    for (int base = beg; base < end; base += 32) {
        int cnt = min(32, end - base);
        int myidx = (lane < cnt) ? d_col[base + lane] : 0;
        for (int e = 0; e < cnt; e += 2) {
            int ee = e + half;
            int s  = __shfl_sync(FULL, myidx, ee);
            if (ee < cnt) {
                float4 v = h4[s * 16 + sub];
                a.x += v.x; a.y += v.y; a.z += v.z; a.w += v.w;
            }
        }
    }
    a.x += __shfl_xor_sync(FULL, a.x, 16);
    a.y += __shfl_xor_sync(FULL, a.y, 16);
    a.z += __shfl_xor_sync(FULL, a.z, 16);
    a.w += __shfl_xor_sync(FULL, a.w, 16);
    float inv = d_invdeg[w];
    a.x *= inv; a.y *= inv; a.z *= inv; a.w *= inv;

    if (half == 0) {
        if (MODE == 1 || MODE == 2) ((float4*)hout)[w * 16 + sub] = a;
        float4* acc4 = (float4*)d_acc;
        float4 t = (MODE == 1) ? h4[w * 16 + sub] : acc4[w * 16 + sub];
        t.x += a.x; t.y += a.y; t.z += a.z; t.w += a.w;
        acc4[w * 16 + sub] = t;
        if (MODE == 4) {
            float4 xs = make_float4(t.x * 0.25f, t.y * 0.25f, t.z * 0.25f, t.w * 0.25f);
            const float4* __restrict__ W4 = (const float4*)Watt;
            float4 wp = W4[sub], wq = W4[16 + sub];
            float pp = xs.x * wp.x + xs.y * wp.y + xs.z * wp.z + xs.w * wp.w;
            float qq = xs.x * wq.x + xs.y * wq.y + xs.z * wq.z + xs.w * wq.w;
#pragma unroll
            for (int off = 8; off; off >>= 1) {
                pp += __shfl_xor_sync(0x0000ffffu, pp, off);
                qq += __shfl_xor_sync(0x0000ffffu, qq, off);
            }
            if (sub == 0) { d_p[w] = pp; d_q[w] = qq; }
        }
    }
}

// ---------------- node GEMM: out[n,M] = (hin[n,64]*scale) @ W[64,M] ----------
template <int M>
__global__ void k_gemm(const float* __restrict__ hin, float scale,
                       const float* __restrict__ W, float* __restrict__ out, int n) {
    constexpr int NPG = 128 / M;
    __shared__ float Wsh[64 * M];
    __shared__ float xr[NPG][64];
    int o  = threadIdx.x % M;
    int ln = threadIdx.x / M;
    for (int idx = threadIdx.x; idx < 64 * M; idx += 128) Wsh[idx] = W[idx];
    __syncthreads();
    for (int base = blockIdx.x * NPG; base < n; base += gridDim.x * NPG) {
        int node = base + ln;
        if (node < n)
            for (int k = o; k < 64; k += M) xr[ln][k] = hin[node * 64 + k] * scale;
        __syncthreads();
        if (node < n) {
            float acc = 0.f;
#pragma unroll
            for (int k = 0; k < 64; k++) acc += xr[ln][k] * Wsh[k * M + o];
            out[node * M + o] = acc;
        }
        __syncthreads();
    }
}

// ---------------- conv1 edge aggregation (64-wide, relu, fused p2/q2) --------
__global__ void k_edge64(const float* __restrict__ g,
                         const float* __restrict__ p, const float* __restrict__ q,
                         const float* __restrict__ batt,
                         const float* __restrict__ Watt2,
                         float* __restrict__ hid,
                         float* __restrict__ pout, float* __restrict__ qout, int n) {
    int w    = (blockIdx.x * blockDim.x + threadIdx.x) >> 5;
    int lane = threadIdx.x & 31;
    if (w >= n) return;
    float qi = q[w] + batt[0];
    int beg = d_rowptr[w], end = d_rowptr[w + 1];
    const float4* __restrict__ g4 = (const float4*)g;
    int half = lane >> 4, sub = lane & 15;
    float4 a = make_float4(0.f, 0.f, 0.f, 0.f);
    for (int base = beg; base < end; base += 32) {
        int cnt = min(32, end - base);
        int myidx = 0; float pv = 0.f;
        if (lane < cnt) {
            myidx = d_col[base + lane];
            float t = p[myidx] + qi;
            pv = t > 0.f ? t : 0.01f * t;   // leaky_relu
        }
        for (int e = 0; e < cnt; e += 2) {
            int ee = e + half;
            int s  = __shfl_sync(FULL, myidx, ee);
            float sc = __shfl_sync(FULL, pv, ee);
            if (ee < cnt) {
                float4 v = g4[s * 16 + sub];
                a.x += sc * v.x; a.y += sc * v.y; a.z += sc * v.z; a.w += sc * v.w;
            }
        }
    }
    a.x += __shfl_xor_sync(FULL, a.x, 16);
    a.y += __shfl_xor_sync(FULL, a.y, 16);
    a.z += __shfl_xor_sync(FULL, a.z, 16);
    a.w += __shfl_xor_sync(FULL, a.w, 16);
    a.x = fmaxf(a.x, 0.f); a.y = fmaxf(a.y, 0.f);
    a.z = fmaxf(a.z, 0.f); a.w = fmaxf(a.w, 0.f);
    if (half == 0) ((float4*)hid)[w * 16 + sub] = a;
    // fused p2/q2: lanes 0-15 -> p (Watt2[:64]), lanes 16-31 -> q (Watt2[64:])
    const float4* __restrict__ W4 = (const float4*)Watt2;
    float4 ww = W4[lane];
    float d = a.x * ww.x + a.y * ww.y + a.z * ww.z + a.w * ww.w;
#pragma unroll
    for (int off = 8; off; off >>= 1) d += __shfl_xor_sync(FULL, d, off);
    if (lane == 0)  pout[w] = d;
    if (lane == 16) qout[w] = d;
}

// ---------------- conv2 edge aggregation (32-wide, quad-gather, final) -------
__global__ void k_edge32(const float* __restrict__ g2,
                         const float* __restrict__ p, const float* __restrict__ q,
                         const float* __restrict__ batt,
                         float* __restrict__ out, int n) {
    int w    = (blockIdx.x * blockDim.x + threadIdx.x) >> 5;
    int lane = threadIdx.x & 31;
    if (w >= n) return;
    float qi = q[w] + batt[0];
    int beg = d_rowptr[w], end = d_rowptr[w + 1];
    const float4* __restrict__ g4 = (const float4*)g2;
    int quad = lane >> 3, sub = lane & 7;
    float4 a = make_float4(0.f, 0.f, 0.f, 0.f);
    for (int base = beg; base < end; base += 32) {
        int cnt = min(32, end - base);
        int myidx = 0; float pv = 0.f;
        if (lane < cnt) {
            myidx = d_col[base + lane];
            float t = p[myidx] + qi;
            pv = t > 0.f ? t : 0.01f * t;
        }
        for (int e = 0; e < cnt; e += 4) {
            int ee = e + quad;
            int s  = __shfl_sync(FULL, myidx, ee);
            float sc = __shfl_sync(FULL, pv, ee);
            if (ee < cnt) {
                float4 v = g4[s * 8 + sub];
                a.x += sc * v.x; a.y += sc * v.y; a.z += sc * v.z; a.w += sc * v.w;
            }
        }
    }
    a.x += __shfl_xor_sync(FULL, a.x, 16);
    a.y += __shfl_xor_sync(FULL, a.y, 16);
    a.z += __shfl_xor_sync(FULL, a.z, 16);
    a.w += __shfl_xor_sync(FULL, a.w, 16);
    a.x += __shfl_xor_sync(FULL, a.x, 8);
    a.y += __shfl_xor_sync(FULL, a.y, 8);
    a.z += __shfl_xor_sync(FULL, a.z, 8);
    a.w += __shfl_xor_sync(FULL, a.w, 8);
    if (lane < 8) ((float4*)out)[w * 8 + sub] = a;
}

// ---------------- launch ------------------------------------------------------
extern "C" void kernel_launch(void* const* d_in, const int* in_sizes, int n_in,
                              void* d_out, int out_size) {
    const float* x     = (const float*)d_in[0];
    const int*   ei    = (const int*)  d_in[1];
    const float* Watt1 = (const float*)d_in[2];
    const float* batt1 = (const float*)d_in[3];
    const float* Wlin1 = (const float*)d_in[4];
    const float* Watt2 = (const float*)d_in[5];
    const float* batt2 = (const float*)d_in[6];
    const float* Wlin2 = (const float*)d_in[7];

    int n = in_sizes[0] / 64;   // 50000
    int e = in_sizes[1] / 2;    // 800000
    const int* src = ei;
    const int* dst = ei + e;

    float *buf0, *buf1, *accp, *gp, *hidp, *g2p, *pp, *qp, *p2p, *q2p;
    cudaGetSymbolAddress((void**)&buf0, d_buf0);
    cudaGetSymbolAddress((void**)&buf1, d_buf1);
    cudaGetSymbolAddress((void**)&accp, d_acc);
    cudaGetSymbolAddress((void**)&gp,   d_g);
    cudaGetSymbolAddress((void**)&hidp, d_hid);
    cudaGetSymbolAddress((void**)&g2p,  d_g2);
    cudaGetSymbolAddress((void**)&pp,   d_p);
    cudaGetSymbolAddress((void**)&qp,   d_q);
    cudaGetSymbolAddress((void**)&p2p,  d_p2);
    cudaGetSymbolAddress((void**)&q2p,  d_q2);

    const int TB = 256;
    int nblk   = (n + TB - 1) / TB;
    int nb1024 = (n + 1023) / 1024;
    int wb     = (n * 32 + TB - 1) / TB;

    // CSR build
    k_zero_cnt<<<nblk, TB>>>(n);
    k_count<<<592, TB>>>(dst, e);
    k_scanA<<<nb1024, 1024>>>(n);
    k_scanB<<<1, 128>>>(nb1024);
    k_scanC<<<nblk, TB>>>(n, e);
    k_fill<<<592, TB>>>(src, dst, e);

    // graphSmoothing (pass3 fuses conv1 p/q with the 0.25 scale)
    k_pass<1><<<wb, TB>>>(x,    buf0, Watt1, n);
    k_pass<2><<<wb, TB>>>(buf0, buf1, Watt1, n);
    k_pass<4><<<wb, TB>>>(buf1, buf0, Watt1, n);

    // conv1
    k_gemm<64><<<592, 128>>>(accp, 0.25f, Wlin1, gp, n);
    k_edge64<<<wb, TB>>>(gp, pp, qp, batt1, Watt2, hidp, p2p, q2p, n);

    // conv2
    k_gemm<32><<<592, 128>>>(hidp, 1.0f, Wlin2, g2p, n);
    k_edge32<<<wb, TB>>>(g2p, p2p, q2p, batt2, (float*)d_out, n);
}